// round 3
// baseline (speedup 1.0000x reference)
#include <cuda_runtime.h>

#define CH   64
#define HH   112
#define WW   112
#define HWS  12544
#define BB   4
#define KK   49
#define NPIX (BB*HWS)
#define NBLK (BB*(HWS/128))      // 392 blocks in k_main == one wave (<= 444 capacity)

// Scratch (device globals — no allocation allowed). Zero-initialized at load.
__device__ __align__(16) float g_y0[BB*CH*HWS];     // reduce output (pre-BN1)
__device__ float g_stats1[2*CH];
__device__ float g_stats2[2*CH];
__device__ unsigned int g_ctr;

// ---------------------------------------------------------------- K1: reduce GEMM + stats1
// y0[b,o,p] = sum_c wred[o,c]*x[b,c,p]. Block: 128 pixels, 256 threads, 8o x 4pix tiles.
// Block (0,0) additionally zeroes g_stats2/g_ctr for the upcoming k_main (replay-safe:
// k_main of the previous replay finished before this kernel starts).
__global__ __launch_bounds__(256) void k_reduce(const float* __restrict__ x,
                                                const float* __restrict__ wred) {
    __shared__ __align__(16) float xs[CH][128];
    __shared__ float ws[CH][CH];
    const int t = threadIdx.x;
    const int b = blockIdx.y;
    const int pix0 = blockIdx.x * 128;

    if (blockIdx.x == 0 && blockIdx.y == 0) {
        if (t < 2*CH) g_stats2[t] = 0.f;
        if (t == 0)   g_ctr = 0u;
    }

    const float* xb = x + (size_t)b*CH*HWS + pix0;
    for (int l = t; l < CH*128; l += 256) {
        int c = l >> 7, p = l & 127;
        xs[c][p] = xb[(size_t)c*HWS + p];
    }
    for (int l = t; l < CH*CH; l += 256) ws[l >> 6][l & 63] = wred[l];
    __syncthreads();

    const int og = t >> 5;
    const int pg = t & 31;
    float acc[8][4];
    #pragma unroll
    for (int i = 0; i < 8; i++)
        #pragma unroll
        for (int j = 0; j < 4; j++) acc[i][j] = 0.f;

    #pragma unroll 4
    for (int c = 0; c < CH; c++) {
        float4 xv = ((const float4*)xs[c])[pg];
        #pragma unroll
        for (int i = 0; i < 8; i++) {
            float w = ws[og*8 + i][c];
            acc[i][0] = fmaf(w, xv.x, acc[i][0]);
            acc[i][1] = fmaf(w, xv.y, acc[i][1]);
            acc[i][2] = fmaf(w, xv.z, acc[i][2]);
            acc[i][3] = fmaf(w, xv.w, acc[i][3]);
        }
    }

    float* y0b = g_y0 + (size_t)b*CH*HWS + pix0;
    #pragma unroll
    for (int i = 0; i < 8; i++) {
        const int o = og*8 + i;
        float4 v; v.x = acc[i][0]; v.y = acc[i][1]; v.z = acc[i][2]; v.w = acc[i][3];
        ((float4*)(y0b + (size_t)o*HWS))[pg] = v;
        float s = v.x + v.y + v.z + v.w;
        float q = v.x*v.x + v.y*v.y + v.z*v.z + v.w*v.w;
        #pragma unroll
        for (int off = 16; off; off >>= 1) {
            s += __shfl_down_sync(0xffffffffu, s, off);
            q += __shfl_down_sync(0xffffffffu, q, off);
        }
        if (pg == 0) {
            atomicAdd(&g_stats1[o], s);
            atomicAdd(&g_stats1[CH + o], q);
        }
    }
}

// ---------------------------------------------------------------- K2: bn1 + span + involution + bn2 + PReLU
// Single-wave kernel (392 blocks, 3/SM guaranteed by launch_bounds+smem) with an
// in-kernel grid barrier separating stats2 accumulation from bn2 finalize.
__global__ __launch_bounds__(256, 3) void k_main(const float* __restrict__ x,
                                                 const float* __restrict__ wspan,
                                                 const float* __restrict__ g1,
                                                 const float* __restrict__ b1,
                                                 const float* __restrict__ g2,
                                                 const float* __restrict__ b2,
                                                 const float* __restrict__ alpha,
                                                 float* __restrict__ out) {
    extern __shared__ __align__(16) float sm[];
    float* ws = sm;                 // [49*64]   span weights
    float* ys = ws + KK*CH;         // [64*128]  bn1-relu'd y0 tile
    float* ks = ys + CH*128;        // [49*128]  per-pixel kernels
    float* bn = ks + KK*128;        // [192]     bn scale/shift (+alpha in epilogue)

    const int t = threadIdx.x;
    const int b = blockIdx.y;
    const int pix0 = blockIdx.x * 128;

    if (t < CH) {
        const float n = (float)NPIX;
        float mean = g_stats1[t] / n;
        float var  = g_stats1[CH + t] / n - mean*mean;
        float sc = g1[t] * rsqrtf(var + 1e-5f);
        bn[t]      = sc;
        bn[CH + t] = b1[t] - mean*sc;
    }
    for (int l = t; l < KK*CH; l += 256) ws[l] = wspan[l];
    __syncthreads();

    const float* y0b = g_y0 + (size_t)b*CH*HWS + pix0;
    for (int l = t; l < CH*128; l += 256) {
        int c = l >> 7, p = l & 127;
        float v = y0b[(size_t)c*HWS + p];
        ys[l] = fmaxf(fmaf(v, bn[c], bn[CH + c]), 0.f);
    }
    __syncthreads();

    // ---- span GEMM: ks[p][pix] = sum_c ws[p][c]*ys[c][pix] (warps 0..6) ----
    {
        const int og = t >> 5;
        const int pg = t & 31;
        if (og < 7) {
            float acc[7][4];
            #pragma unroll
            for (int i = 0; i < 7; i++)
                #pragma unroll
                for (int j = 0; j < 4; j++) acc[i][j] = 0.f;
            #pragma unroll 4
            for (int c = 0; c < CH; c++) {
                float4 xv = ((const float4*)(ys + c*128))[pg];
                #pragma unroll
                for (int i = 0; i < 7; i++) {
                    float w = ws[(og*7 + i)*CH + c];
                    acc[i][0] = fmaf(w, xv.x, acc[i][0]);
                    acc[i][1] = fmaf(w, xv.y, acc[i][1]);
                    acc[i][2] = fmaf(w, xv.z, acc[i][2]);
                    acc[i][3] = fmaf(w, xv.w, acc[i][3]);
                }
            }
            #pragma unroll
            for (int i = 0; i < 7; i++) {
                float4 v; v.x = acc[i][0]; v.y = acc[i][1]; v.z = acc[i][2]; v.w = acc[i][3];
                ((float4*)(ks + (og*7 + i)*128))[pg] = v;
            }
        }
    }
    __syncthreads();

    // ---- involution (accumulators stay in registers through the barrier) ----
    const int wg = t & 31;          // float4 pixel group
    const int cl = t >> 5;          // channel lane: channels cl*8 .. cl*8+7
    const int pp = pix0 + wg*4;
    const int h  = pp / WW;
    const int w0 = pp - h*WW;

    float acc[8][4];
    #pragma unroll
    for (int cc = 0; cc < 8; cc++)
        #pragma unroll
        for (int j = 0; j < 4; j++) acc[cc][j] = 0.f;

    {
        const float* xbase = x + ((size_t)b*CH + cl*8)*HWS;
        const float4 zero4 = make_float4(0.f, 0.f, 0.f, 0.f);
        #pragma unroll
        for (int kh = 0; kh < 7; kh++) {
            const int row = h + kh - 3;
            if (row < 0 || row >= HH) continue;
            float4 kv[7];
            #pragma unroll
            for (int kw = 0; kw < 7; kw++)
                kv[kw] = ((const float4*)(ks + (kh*7 + kw)*128))[wg];
            const float* xrow = xbase + (size_t)row*WW;
            #pragma unroll
            for (int cc = 0; cc < 8; cc++) {
                const float* xc = xrow + (size_t)cc*HWS;
                float4 v1 = *(const float4*)(xc + w0);
                float4 v0 = (w0 >= 4)   ? *(const float4*)(xc + w0 - 4) : zero4;
                float4 v2 = (w0 <= 104) ? *(const float4*)(xc + w0 + 4) : zero4;
                float xr[10] = {v0.y, v0.z, v0.w, v1.x, v1.y, v1.z, v1.w, v2.x, v2.y, v2.z};
                #pragma unroll
                for (int kw = 0; kw < 7; kw++) {
                    acc[cc][0] = fmaf(xr[0 + kw], kv[kw].x, acc[cc][0]);
                    acc[cc][1] = fmaf(xr[1 + kw], kv[kw].y, acc[cc][1]);
                    acc[cc][2] = fmaf(xr[2 + kw], kv[kw].z, acc[cc][2]);
                    acc[cc][3] = fmaf(xr[3 + kw], kv[kw].w, acc[cc][3]);
                }
            }
        }
    }

    // ---- stats2: warp shuffle reduce + global atomics ----
    #pragma unroll
    for (int cc = 0; cc < 8; cc++) {
        float s = acc[cc][0] + acc[cc][1] + acc[cc][2] + acc[cc][3];
        float q = acc[cc][0]*acc[cc][0] + acc[cc][1]*acc[cc][1]
                + acc[cc][2]*acc[cc][2] + acc[cc][3]*acc[cc][3];
        #pragma unroll
        for (int off = 16; off; off >>= 1) {
            s += __shfl_down_sync(0xffffffffu, s, off);
            q += __shfl_down_sync(0xffffffffu, q, off);
        }
        if (wg == 0) {
            atomicAdd(&g_stats2[cl*8 + cc], s);
            atomicAdd(&g_stats2[CH + cl*8 + cc], q);
        }
    }

    // ---- grid barrier (single wave: all 392 blocks co-resident) ----
    __threadfence();
    __syncthreads();
    if (t == 0) {
        atomicAdd(&g_ctr, 1u);
        volatile unsigned int* ctr = &g_ctr;
        while (*ctr < (unsigned)NBLK) __nanosleep(64);
    }
    __syncthreads();
    __threadfence();

    // ---- bn2 finalize (L2-coherent reads) + PReLU epilogue ----
    if (t < CH) {
        const float n = (float)NPIX;
        float ssum = *(volatile float*)&g_stats2[t];
        float sq   = *(volatile float*)&g_stats2[CH + t];
        float mean = ssum / n;
        float var  = sq / n - mean*mean;
        float sc = g2[t] * rsqrtf(var + 1e-3f);
        bn[t]        = sc;
        bn[CH + t]   = b2[t] - mean*sc;
        bn[2*CH + t] = alpha[t];
    }
    if (blockIdx.x == 0 && blockIdx.y == 0 && t < 2*CH) g_stats1[t] = 0.f;  // for next replay
    __syncthreads();

    float* ob = out + ((size_t)b*CH + cl*8)*HWS + pp;
    #pragma unroll
    for (int cc = 0; cc < 8; cc++) {
        const int c = cl*8 + cc;
        float sc = bn[c], sh = bn[CH + c], al = bn[2*CH + c];
        float4 v;
        float u;
        u = fmaf(acc[cc][0], sc, sh); v.x = u > 0.f ? u : al*u;
        u = fmaf(acc[cc][1], sc, sh); v.y = u > 0.f ? u : al*u;
        u = fmaf(acc[cc][2], sc, sh); v.z = u > 0.f ? u : al*u;
        u = fmaf(acc[cc][3], sc, sh); v.w = u > 0.f ? u : al*u;
        *((float4*)(ob + (size_t)cc*HWS)) = v;
    }
}

// ----------------------------------------------------------------
extern "C" void kernel_launch(void* const* d_in, const int* in_sizes, int n_in,
                              void* d_out, int out_size) {
    const float* x     = (const float*)d_in[0];
    const float* wred  = (const float*)d_in[1];
    const float* g1    = (const float*)d_in[2];
    const float* b1    = (const float*)d_in[3];
    const float* wspan = (const float*)d_in[4];
    const float* g2    = (const float*)d_in[5];
    const float* b2    = (const float*)d_in[6];
    const float* alpha = (const float*)d_in[7];
    float* out = (float*)d_out;

    const int smem_main = (KK*CH + CH*128 + KK*128 + 192) * sizeof(float); // 71168 B
    cudaFuncSetAttribute(k_main, cudaFuncAttributeMaxDynamicSharedMemorySize, smem_main);

    k_reduce<<<dim3(HWS/128, BB), 256>>>(x, wred);
    k_main  <<<dim3(HWS/128, BB), 256, smem_main>>>(x, wspan, g1, b1, g2, b2, alpha, out);
}

// round 4
// speedup vs baseline: 1.0481x; 1.0481x over previous
#include <cuda_runtime.h>

#define CH   64
#define HH   112
#define WW   112
#define HWS  12544
#define BB   4
#define KK   49
#define NPIX (BB*HWS)

// Scratch (device globals — no allocation allowed). Zero-initialized at load.
__device__ __align__(16) float g_y0  [BB*CH*HWS];   // reduce output (pre-BN1)
__device__ __align__(16) float g_out0[BB*CH*HWS];   // involution output (pre-BN2)
__device__ float g_stats1[2*CH];
__device__ float g_stats2[2*CH];

// ---------------------------------------------------------------- K1: reduce GEMM + stats1
// y0[b,o,p] = sum_c wred[o,c]*x[b,c,p]. Block: 128 pixels, 256 threads, 8o x 4pix tiles.
// Block (0,0) zeroes g_stats2 for this replay (k_main, which accumulates it, runs after).
__global__ __launch_bounds__(256) void k_reduce(const float* __restrict__ x,
                                                const float* __restrict__ wred) {
    __shared__ __align__(16) float xs[CH][128];
    __shared__ __align__(16) float ws[CH][CH];
    const int t = threadIdx.x;
    const int b = blockIdx.y;
    const int pix0 = blockIdx.x * 128;

    if (blockIdx.x == 0 && blockIdx.y == 0 && t < 2*CH) g_stats2[t] = 0.f;

    #pragma unroll
    for (int l = t; l < CH*32; l += 256) {
        int c = l >> 5, p4 = l & 31;
        ((float4*)xs[c])[p4] = *(const float4*)(x + ((size_t)b*CH + c)*HWS + pix0 + p4*4);
    }
    #pragma unroll
    for (int l = t; l < CH*CH/4; l += 256)
        ((float4*)ws)[l] = ((const float4*)wred)[l];
    __syncthreads();

    const int og = t >> 5;
    const int pg = t & 31;
    float acc[8][4];
    #pragma unroll
    for (int i = 0; i < 8; i++)
        #pragma unroll
        for (int j = 0; j < 4; j++) acc[i][j] = 0.f;

    #pragma unroll 4
    for (int c = 0; c < CH; c++) {
        float4 xv = ((const float4*)xs[c])[pg];
        #pragma unroll
        for (int i = 0; i < 8; i++) {
            float w = ws[og*8 + i][c];
            acc[i][0] = fmaf(w, xv.x, acc[i][0]);
            acc[i][1] = fmaf(w, xv.y, acc[i][1]);
            acc[i][2] = fmaf(w, xv.z, acc[i][2]);
            acc[i][3] = fmaf(w, xv.w, acc[i][3]);
        }
    }

    float* y0b = g_y0 + (size_t)b*CH*HWS + pix0;
    #pragma unroll
    for (int i = 0; i < 8; i++) {
        const int o = og*8 + i;
        float4 v; v.x = acc[i][0]; v.y = acc[i][1]; v.z = acc[i][2]; v.w = acc[i][3];
        ((float4*)(y0b + (size_t)o*HWS))[pg] = v;
        float s = v.x + v.y + v.z + v.w;
        float q = v.x*v.x + v.y*v.y + v.z*v.z + v.w*v.w;
        #pragma unroll
        for (int off = 16; off; off >>= 1) {
            s += __shfl_down_sync(0xffffffffu, s, off);
            q += __shfl_down_sync(0xffffffffu, q, off);
        }
        if (pg == 0) {
            atomicAdd(&g_stats1[o], s);
            atomicAdd(&g_stats1[CH + o], q);
        }
    }
}

// ---------------------------------------------------------------- K2: bn1 + span GEMM + involution + stats2
__global__ __launch_bounds__(256, 3) void k_main(const float* __restrict__ x,
                                                 const float* __restrict__ wspan,
                                                 const float* __restrict__ g1,
                                                 const float* __restrict__ b1) {
    extern __shared__ __align__(16) float sm[];
    float* ws = sm;                 // [49*64]   span weights
    float* ys = ws + KK*CH;         // [64*128]  bn1-relu'd y0 tile
    float* ks = ys + CH*128;        // [49*128]  per-pixel kernels
    float* bn = ks + KK*128;        // [128]     bn1 scale/shift

    const int t = threadIdx.x;
    const int b = blockIdx.y;
    const int pix0 = blockIdx.x * 128;

    if (t < CH) {
        const float n = (float)NPIX;
        float mean = g_stats1[t] / n;
        float var  = g_stats1[CH + t] / n - mean*mean;
        float sc = g1[t] * rsqrtf(var + 1e-5f);
        bn[t]      = sc;
        bn[CH + t] = b1[t] - mean*sc;
    }
    #pragma unroll
    for (int l = t; l < KK*CH/4; l += 256)
        ((float4*)ws)[l] = ((const float4*)wspan)[l];
    __syncthreads();

    #pragma unroll
    for (int l = t; l < CH*32; l += 256) {
        int c = l >> 5, p4 = l & 31;
        float4 v = *(const float4*)(g_y0 + ((size_t)b*CH + c)*HWS + pix0 + p4*4);
        float sc = bn[c], sh = bn[CH + c];
        v.x = fmaxf(fmaf(v.x, sc, sh), 0.f);
        v.y = fmaxf(fmaf(v.y, sc, sh), 0.f);
        v.z = fmaxf(fmaf(v.z, sc, sh), 0.f);
        v.w = fmaxf(fmaf(v.w, sc, sh), 0.f);
        ((float4*)(ys + c*128))[p4] = v;
    }
    __syncthreads();

    // ---- span GEMM: ks[p][pix] = sum_c ws[p][c]*ys[c][pix] (warps 0..6) ----
    {
        const int og = t >> 5;
        const int pg = t & 31;
        if (og < 7) {
            float acc[7][4];
            #pragma unroll
            for (int i = 0; i < 7; i++)
                #pragma unroll
                for (int j = 0; j < 4; j++) acc[i][j] = 0.f;
            #pragma unroll 4
            for (int c = 0; c < CH; c++) {
                float4 xv = ((const float4*)(ys + c*128))[pg];
                #pragma unroll
                for (int i = 0; i < 7; i++) {
                    float w = ws[(og*7 + i)*CH + c];
                    acc[i][0] = fmaf(w, xv.x, acc[i][0]);
                    acc[i][1] = fmaf(w, xv.y, acc[i][1]);
                    acc[i][2] = fmaf(w, xv.z, acc[i][2]);
                    acc[i][3] = fmaf(w, xv.w, acc[i][3]);
                }
            }
            #pragma unroll
            for (int i = 0; i < 7; i++) {
                float4 v; v.x = acc[i][0]; v.y = acc[i][1]; v.z = acc[i][2]; v.w = acc[i][3];
                ((float4*)(ks + (og*7 + i)*128))[pg] = v;
            }
        }
    }
    __syncthreads();

    // ---- involution ----
    const int wg = t & 31;
    const int cl = t >> 5;
    const int pp = pix0 + wg*4;
    const int h  = pp / WW;
    const int w0 = pp - h*WW;

    float acc[8][4];
    #pragma unroll
    for (int cc = 0; cc < 8; cc++)
        #pragma unroll
        for (int j = 0; j < 4; j++) acc[cc][j] = 0.f;

    {
        const float* xbase = x + ((size_t)b*CH + cl*8)*HWS;
        const float4 zero4 = make_float4(0.f, 0.f, 0.f, 0.f);
        #pragma unroll
        for (int kh = 0; kh < 7; kh++) {
            const int row = h + kh - 3;
            if (row < 0 || row >= HH) continue;
            float4 kv[7];
            #pragma unroll
            for (int kw = 0; kw < 7; kw++)
                kv[kw] = ((const float4*)(ks + (kh*7 + kw)*128))[wg];
            const float* xrow = xbase + (size_t)row*WW;
            #pragma unroll
            for (int cc = 0; cc < 8; cc++) {
                const float* xc = xrow + (size_t)cc*HWS;
                float4 v1 = *(const float4*)(xc + w0);
                float4 v0 = (w0 >= 4)   ? *(const float4*)(xc + w0 - 4) : zero4;
                float4 v2 = (w0 <= 104) ? *(const float4*)(xc + w0 + 4) : zero4;
                float xr[10] = {v0.y, v0.z, v0.w, v1.x, v1.y, v1.z, v1.w, v2.x, v2.y, v2.z};
                #pragma unroll
                for (int kw = 0; kw < 7; kw++) {
                    acc[cc][0] = fmaf(xr[0 + kw], kv[kw].x, acc[cc][0]);
                    acc[cc][1] = fmaf(xr[1 + kw], kv[kw].y, acc[cc][1]);
                    acc[cc][2] = fmaf(xr[2 + kw], kv[kw].z, acc[cc][2]);
                    acc[cc][3] = fmaf(xr[3 + kw], kv[kw].w, acc[cc][3]);
                }
            }
        }
    }

    float* ob = g_out0 + ((size_t)b*CH + cl*8)*HWS + pp;
    #pragma unroll
    for (int cc = 0; cc < 8; cc++) {
        float4 v; v.x = acc[cc][0]; v.y = acc[cc][1]; v.z = acc[cc][2]; v.w = acc[cc][3];
        *((float4*)(ob + (size_t)cc*HWS)) = v;
        float s = v.x + v.y + v.z + v.w;
        float q = v.x*v.x + v.y*v.y + v.z*v.z + v.w*v.w;
        #pragma unroll
        for (int off = 16; off; off >>= 1) {
            s += __shfl_down_sync(0xffffffffu, s, off);
            q += __shfl_down_sync(0xffffffffu, q, off);
        }
        if (wg == 0) {
            atomicAdd(&g_stats2[cl*8 + cc], s);
            atomicAdd(&g_stats2[CH + cl*8 + cc], q);
        }
    }
}

// ---------------------------------------------------------------- K3: bn2 finalize + affine + PReLU
// One block per (b,c) image-channel: no per-element index math, deep MLP.
// Block 0 also zeroes g_stats1 for the next replay (k_main already consumed it).
__global__ __launch_bounds__(256) void k_apply(const float* __restrict__ gamma,
                                               const float* __restrict__ beta,
                                               const float* __restrict__ alpha,
                                               float* __restrict__ out) {
    __shared__ float s_p[3];
    const int t = threadIdx.x;
    const int bc = blockIdx.x;          // b*CH + c
    const int c = bc & (CH-1);

    if (t == 0) {
        const float n = (float)NPIX;
        float mean = g_stats2[c] / n;
        float var  = g_stats2[CH + c] / n - mean*mean;
        float sc = gamma[c] * rsqrtf(var + 1e-3f);
        s_p[0] = sc;
        s_p[1] = beta[c] - mean*sc;
        s_p[2] = alpha[c];
    }
    if (bc == 0 && t < 2*CH) g_stats1[t] = 0.f;
    __syncthreads();

    const float sc = s_p[0], sh = s_p[1], al = s_p[2];
    const float4* src = (const float4*)(g_out0 + (size_t)bc*HWS);
    float4* dst = (float4*)(out + (size_t)bc*HWS);
    #pragma unroll 4
    for (int i = t; i < HWS/4; i += 256) {
        float4 v = src[i];
        float u;
        u = fmaf(v.x, sc, sh); v.x = u > 0.f ? u : al*u;
        u = fmaf(v.y, sc, sh); v.y = u > 0.f ? u : al*u;
        u = fmaf(v.z, sc, sh); v.z = u > 0.f ? u : al*u;
        u = fmaf(v.w, sc, sh); v.w = u > 0.f ? u : al*u;
        dst[i] = v;
    }
}

// ----------------------------------------------------------------
extern "C" void kernel_launch(void* const* d_in, const int* in_sizes, int n_in,
                              void* d_out, int out_size) {
    const float* x     = (const float*)d_in[0];
    const float* wred  = (const float*)d_in[1];
    const float* g1    = (const float*)d_in[2];
    const float* b1    = (const float*)d_in[3];
    const float* wspan = (const float*)d_in[4];
    const float* g2    = (const float*)d_in[5];
    const float* b2    = (const float*)d_in[6];
    const float* alpha = (const float*)d_in[7];
    float* out = (float*)d_out;

    const int smem_main = (KK*CH + CH*128 + KK*128 + 128) * sizeof(float); // 70912 B
    cudaFuncSetAttribute(k_main, cudaFuncAttributeMaxDynamicSharedMemorySize, smem_main);

    k_reduce<<<dim3(HWS/128, BB), 256>>>(x, wred);
    k_main  <<<dim3(HWS/128, BB), 256, smem_main>>>(x, wspan, g1, b1);
    k_apply <<<BB*CH, 256>>>(g2, b2, alpha, out);
}